// round 13
// baseline (speedup 1.0000x reference)
#include <cuda_runtime.h>
#include <cuda_fp16.h>
#include <cstdint>

#define HIDDEN 128
#define MAX_NODES 100000
#define MAX_EDGES 800000
#define NBINS_MAX 1600
#define NODES_PER_CTA 64
#define PROJ_THREADS 512

// Interleaved per-node projections, fp16, COLUMN-PERMUTED for dense stores:
// row = [src-proj(+b1) perm | dst-proj perm]. Permutation compensated by g_w2p.
__device__ __half g_p[(size_t)MAX_NODES * 256];
__device__ float  g_w2p[128];     // W2 permuted to stored order

// Edge sort scratch (zero-initialized at module load; g_hist re-zeroed by the
// tail of each launch's edge kernel so every replay sees a clean histogram).
__device__ int  g_hist[NBINS_MAX];
__device__ int  g_bincur[NBINS_MAX];
__device__ int4 g_esort[MAX_EDGES];     // {src, dst, edge_id, 0} bucketed by src>>6

__device__ __forceinline__ uint32_t smem_u32(const void* p) {
    uint32_t a;
    asm("{ .reg .u64 t; cvta.to.shared.u64 t, %1; cvt.u32.u64 %0, t; }"
        : "=r"(a) : "l"(p));
    return a;
}

// SMEM layout (dynamic, 98816 B, 1 CTA x 512 thr per SM):
//   [0,512)         b1 (128 f32)
//   [512,16896)     A0: z fp16, 64 rows x 256B, XOR-16B swizzle
//   [16896,33280)   A1: double buffer
//   [33280,98816)   B: W1^T fp16, 256 rows x 256B, XOR-16B swizzle (persistent)
#define SM_B1  0
#define SM_A0  512
#define SM_A1  16896
#define SM_B   33280
#define SMEM_BYTES 98816

// ---------------------------------------------------------------------------
// Phase 1: persistent 512-thread CTA, warp grid 2m x 8n (R11 verbatim, 28.1us).
// ---------------------------------------------------------------------------
__global__ void __launch_bounds__(PROJ_THREADS, 1)
proj_mma_kernel(const float* __restrict__ z,
                const float* __restrict__ W1,
                const float* __restrict__ b1,
                const float* __restrict__ W2,
                int n_nodes, int n_tiles)
{
    extern __shared__ char smem[];
    const uint32_t smem_base = smem_u32(smem);
    const int tid  = threadIdx.x;
    const int lane = tid & 31;
    const int wid  = tid >> 5;
    const int wm = wid >> 3;      // 0..1  (rows 32*wm)
    const int wn = wid & 7;       // 0..7  (cols 32*wn)

    const int zrow = tid >> 3;
    const int zc4  = (tid & 7) * 4;

    float4 zr[4];
    {
        int node0 = blockIdx.x * NODES_PER_CTA;
        int gn = node0 + zrow; if (gn >= n_nodes) gn = n_nodes - 1;
        const float4* zp = (const float4*)(z + (size_t)gn * HIDDEN);
        #pragma unroll
        for (int j = 0; j < 4; j++) zr[j] = zp[zc4 + j];
    }

    if (tid < 128) ((float*)(smem + SM_B1))[tid] = b1[tid];

    // Permuted W2: stored s within 32-col block: s = q*8 + nj*2 + t
    if (blockIdx.x == 0 && tid < 128) {
        int blk = tid >> 5, s = tid & 31;
        int orig = ((s >> 1) & 3) * 8 + (s >> 3) * 2 + (s & 1);
        g_w2p[tid] = W2[blk * 32 + orig];
    }

    // Stage B once: B[n][k] = W1[k][n] (n<128) / W1[128+k][n-128]
    {
        int n = tid >> 1;
        int c = n & 127;
        int rbase = (n < 128) ? 0 : 128;
        int kc0 = (tid & 1) * 16;
        #pragma unroll 4
        for (int kk = 0; kk < 16; kk++) {
            int kc = kc0 + kk;
            float f0 = W1[(size_t)(rbase + kc * 4 + 0) * 128 + c];
            float f1 = W1[(size_t)(rbase + kc * 4 + 1) * 128 + c];
            float f2 = W1[(size_t)(rbase + kc * 4 + 2) * 128 + c];
            float f3 = W1[(size_t)(rbase + kc * 4 + 3) * 128 + c];
            __half2 h01 = __floats2half2_rn(f0, f1);
            __half2 h23 = __floats2half2_rn(f2, f3);
            uint2 v;
            v.x = *(uint32_t*)&h01;
            v.y = *(uint32_t*)&h23;
            uint32_t off = ((uint32_t)(kc * 8)) ^ ((uint32_t)(n & 7) << 4);
            *(uint2*)(smem + SM_B + n * 256 + off) = v;
        }
    }
    __syncthreads();

    float bx[4], by[4];
    #pragma unroll
    for (int nj = 0; nj < 4; nj++) {
        int col = wn * 32 + nj * 8 + ((lane & 3) << 1);
        if (col < 128) {
            float2 bb = *(const float2*)(smem + SM_B1 + col * 4);
            bx[nj] = bb.x; by[nj] = bb.y;
        } else {
            bx[nj] = 0.f; by[nj] = 0.f;
        }
    }

    const uint32_t smB = smem_base + SM_B;
    int buf = 0;

    for (int tile = blockIdx.x; tile < n_tiles; tile += gridDim.x) {
        const int node0 = tile * NODES_PER_CTA;
        const uint32_t smA = smem_base + (buf ? SM_A1 : SM_A0);

        #pragma unroll
        for (int j = 0; j < 4; j++) {
            int c4 = zc4 + j;
            __half2 h01 = __floats2half2_rn(zr[j].x, zr[j].y);
            __half2 h23 = __floats2half2_rn(zr[j].z, zr[j].w);
            uint2 v;
            v.x = *(uint32_t*)&h01;
            v.y = *(uint32_t*)&h23;
            uint32_t off = ((uint32_t)(c4 * 8)) ^ ((uint32_t)(zrow & 7) << 4);
            *(uint2*)(smem + (buf ? SM_A1 : SM_A0) + zrow * 256 + off) = v;
        }
        __syncthreads();

        {
            int nt = tile + gridDim.x;
            if (nt < n_tiles) {
                int gn = nt * NODES_PER_CTA + zrow;
                if (gn >= n_nodes) gn = n_nodes - 1;
                const float4* zp = (const float4*)(z + (size_t)gn * HIDDEN);
                #pragma unroll
                for (int j = 0; j < 4; j++) zr[j] = zp[zc4 + j];
            }
        }

        float acc[2][4][4];
        #pragma unroll
        for (int mi = 0; mi < 2; mi++)
            #pragma unroll
            for (int nj = 0; nj < 4; nj++)
                #pragma unroll
                for (int q = 0; q < 4; q++) acc[mi][nj][q] = 0.0f;

        #pragma unroll
        for (int ks = 0; ks < 8; ks++) {
            uint32_t a[2][4];
            #pragma unroll
            for (int mi = 0; mi < 2; mi++) {
                int r = wm * 32 + mi * 16 + (lane & 15);
                uint32_t kb = (uint32_t)(ks * 32 + ((lane >> 4) << 4));
                uint32_t addr = smA + (uint32_t)(r * 256) + (kb ^ ((uint32_t)(r & 7) << 4));
                asm volatile("ldmatrix.sync.aligned.m8n8.x4.shared.b16 {%0,%1,%2,%3}, [%4];"
                             : "=r"(a[mi][0]), "=r"(a[mi][1]), "=r"(a[mi][2]), "=r"(a[mi][3])
                             : "r"(addr));
            }
            uint32_t b[4][2];
            #pragma unroll
            for (int nj = 0; nj < 4; nj++) {
                int r = wn * 32 + nj * 8 + (lane & 7);
                uint32_t kb = (uint32_t)(ks * 32 + (((lane >> 3) & 1) << 4));
                uint32_t addr = smB + (uint32_t)(r * 256) + (kb ^ ((uint32_t)(r & 7) << 4));
                asm volatile("ldmatrix.sync.aligned.m8n8.x2.shared.b16 {%0,%1}, [%2];"
                             : "=r"(b[nj][0]), "=r"(b[nj][1]) : "r"(addr));
            }
            #pragma unroll
            for (int mi = 0; mi < 2; mi++)
                #pragma unroll
                for (int nj = 0; nj < 4; nj++) {
                    asm volatile(
                        "mma.sync.aligned.m16n8k16.row.col.f32.f16.f16.f32 "
                        "{%0,%1,%2,%3}, {%4,%5,%6,%7}, {%8,%9}, {%0,%1,%2,%3};"
                        : "+f"(acc[mi][nj][0]), "+f"(acc[mi][nj][1]),
                          "+f"(acc[mi][nj][2]), "+f"(acc[mi][nj][3])
                        : "r"(a[mi][0]), "r"(a[mi][1]), "r"(a[mi][2]), "r"(a[mi][3]),
                          "r"(b[nj][0]), "r"(b[nj][1]));
                }
        }

        {
            const int q = lane & 3;
            #pragma unroll
            for (int mi = 0; mi < 2; mi++) {
                int row = wm * 32 + mi * 16 + (lane >> 2);
                int gn0 = node0 + row;
                int gn1 = gn0 + 8;
                uint32_t p0[4], p1[4];
                #pragma unroll
                for (int nj = 0; nj < 4; nj++) {
                    __half2 v0 = __floats2half2_rn(acc[mi][nj][0] + bx[nj],
                                                   acc[mi][nj][1] + by[nj]);
                    __half2 v1 = __floats2half2_rn(acc[mi][nj][2] + bx[nj],
                                                   acc[mi][nj][3] + by[nj]);
                    p0[nj] = *(uint32_t*)&v0;
                    p1[nj] = *(uint32_t*)&v1;
                }
                size_t base0 = (size_t)gn0 * 256 + wn * 32 + q * 8;
                size_t base1 = (size_t)gn1 * 256 + wn * 32 + q * 8;
                if (gn0 < n_nodes) *(uint4*)(g_p + base0) = *(uint4*)p0;
                if (gn1 < n_nodes) *(uint4*)(g_p + base1) = *(uint4*)p1;
            }
        }
        buf ^= 1;
    }
}

// ---------------------------------------------------------------------------
// Sort pipeline: bucket edges by src tile (bin = src >> 6).
// ---------------------------------------------------------------------------
__global__ void hist_kernel(const int* __restrict__ ei, int n_edges)
{
    int e = blockIdx.x * blockDim.x + threadIdx.x;
    if (e < n_edges) atomicAdd(&g_hist[ei[e] >> 6], 1);
}

__global__ void __launch_bounds__(1024) scan_kernel(int nbins)
{
    __shared__ int sh[NBINS_MAX];
    for (int i = threadIdx.x; i < NBINS_MAX; i += 1024)
        sh[i] = (i < nbins) ? g_hist[i] : 0;
    __syncthreads();
    if (threadIdx.x < 32) {
        int lane = threadIdx.x;
        int run = 0;
        for (int c0 = 0; c0 < nbins; c0 += 32) {
            int i = c0 + lane;
            int orig = (i < nbins) ? sh[i] : 0;
            int v = orig;
            #pragma unroll
            for (int o = 1; o < 32; o <<= 1) {
                int u = __shfl_up_sync(0xFFFFFFFFu, v, o);
                if (lane >= o) v += u;
            }
            if (i < nbins) g_bincur[i] = run + v - orig;   // exclusive prefix
            run += __shfl_sync(0xFFFFFFFFu, v, 31);
        }
    }
}

__global__ void scatter_kernel(const int* __restrict__ ei, int n_edges)
{
    int e = blockIdx.x * blockDim.x + threadIdx.x;
    if (e < n_edges) {
        int s = ei[e];
        int d = ei[n_edges + e];
        int pos = atomicAdd(&g_bincur[s >> 6], 1);
        g_esort[pos] = make_int4(s, d, e, 0);
    }
}

// ---------------------------------------------------------------------------
// Phase 2: EIGHT sorted edges per warp; each half-warp owns 4. Consecutive
// warps process one src tile (32KB) -> src gathers mostly L1-hit. Per-edge
// math/order identical to R8 (bit-identical results). Scores scattered back
// to original edge order. Block 0 re-zeroes g_hist for the next replay.
// ---------------------------------------------------------------------------
__global__ void __launch_bounds__(256) edge_kernel(
    const float* __restrict__ b2,
    float* __restrict__ out,
    int n_edges)
{
    // g_hist already consumed by scan_kernel this launch; reset for next one.
    if (blockIdx.x == 0)
        for (int i = threadIdx.x; i < NBINS_MAX; i += blockDim.x) g_hist[i] = 0;

    int warp = (int)((blockIdx.x * (unsigned)blockDim.x + threadIdx.x) >> 5);
    int lane = threadIdx.x & 31;
    int p0 = warp * 8;
    if (p0 >= n_edges) return;

    int half = lane >> 4;         // 0/1
    int kl   = lane & 15;
    int pe = p0 + half * 4;       // this half-warp's first sorted position

    int sv[4], dv[4], ov[4];
    #pragma unroll
    for (int j = 0; j < 4; j++) {
        int idx = pe + j; if (idx >= n_edges) idx = n_edges - 1;
        int4 en = g_esort[idx];   // uniform across half-warp (broadcast)
        sv[j] = en.x; dv[j] = en.y; ov[j] = en.z;
    }

    // 8 independent 16B gathers (src side L1-resident after sort).
    uint4 ra[4], rb[4];
    #pragma unroll
    for (int j = 0; j < 4; j++)
        ra[j] = *(const uint4*)(g_p + (size_t)sv[j] * 256 + kl * 8);
    #pragma unroll
    for (int j = 0; j < 4; j++)
        rb[j] = *(const uint4*)(g_p + (size_t)dv[j] * 256 + 128 + kl * 8);

    const float4 w0 = *((const float4*)g_w2p + kl * 2);
    const float4 w1 = *((const float4*)g_w2p + kl * 2 + 1);
    const __half2 z2 = __float2half2_rn(0.0f);

    float accv[4];
    #pragma unroll
    for (int j = 0; j < 4; j++) {
        __half2 h0 = __hmax2(__hadd2(*(const __half2*)&ra[j].x, *(const __half2*)&rb[j].x), z2);
        __half2 h1 = __hmax2(__hadd2(*(const __half2*)&ra[j].y, *(const __half2*)&rb[j].y), z2);
        __half2 h2 = __hmax2(__hadd2(*(const __half2*)&ra[j].z, *(const __half2*)&rb[j].z), z2);
        __half2 h3 = __hmax2(__hadd2(*(const __half2*)&ra[j].w, *(const __half2*)&rb[j].w), z2);
        float2 f0 = __half22float2(h0), f1 = __half22float2(h1);
        float2 f2 = __half22float2(h2), f3 = __half22float2(h3);
        float a =       f0.x * w0.x;
        a = fmaf(f0.y, w0.y, a);
        a = fmaf(f1.x, w0.z, a);
        a = fmaf(f1.y, w0.w, a);
        a = fmaf(f2.x, w1.x, a);
        a = fmaf(f2.y, w1.y, a);
        a = fmaf(f3.x, w1.z, a);
        a = fmaf(f3.y, w1.w, a);
        accv[j] = a;
    }

    #pragma unroll
    for (int o = 8; o > 0; o >>= 1) {
        accv[0] += __shfl_xor_sync(0xFFFFFFFFu, accv[0], o);
        accv[1] += __shfl_xor_sync(0xFFFFFFFFu, accv[1], o);
        accv[2] += __shfl_xor_sync(0xFFFFFFFFu, accv[2], o);
        accv[3] += __shfl_xor_sync(0xFFFFFFFFu, accv[3], o);
    }

    if (kl == 0) {
        float bb = b2[0];
        #pragma unroll
        for (int j = 0; j < 4; j++)
            if (pe + j < n_edges) out[ov[j]] = accv[j] + bb;
    }
}

// ---------------------------------------------------------------------------
// Launch
// Inputs: 0 z[f32 N*128], 1 edge_index[i32 2*E], 2 W1[f32 256*128],
//         3 b1[f32 128], 4 W2[f32 128], 5 b2[f32 1]; out f32 [E].
// ---------------------------------------------------------------------------
extern "C" void kernel_launch(void* const* d_in, const int* in_sizes, int n_in,
                              void* d_out, int out_size)
{
    const float* z  = (const float*)d_in[0];
    const int*   ei = (const int*)d_in[1];
    const float* W1 = (const float*)d_in[2];
    const float* b1 = (const float*)d_in[3];
    const float* W2 = (const float*)d_in[4];
    const float* b2 = (const float*)d_in[5];
    float*       out = (float*)d_out;

    int n_nodes = in_sizes[0] / HIDDEN;
    int n_edges = in_sizes[1] / 2;
    int n_tiles = (n_nodes + NODES_PER_CTA - 1) / NODES_PER_CTA;
    int nbins   = (n_nodes + 63) >> 6;

    cudaFuncSetAttribute(proj_mma_kernel,
                         cudaFuncAttributeMaxDynamicSharedMemorySize, SMEM_BYTES);

    int pg = 148;
    if (pg > n_tiles) pg = n_tiles;
    proj_mma_kernel<<<pg, PROJ_THREADS, SMEM_BYTES>>>(z, W1, b1, W2, n_nodes, n_tiles);

    int gb = (n_edges + 255) / 256;
    hist_kernel<<<gb, 256>>>(ei, n_edges);
    scan_kernel<<<1, 1024>>>(nbins);
    scatter_kernel<<<gb, 256>>>(ei, n_edges);

    int eb = (n_edges + 63) / 64;     // 64 edges per 256-thread block
    edge_kernel<<<eb, 256>>>(b2, out, n_edges);
}

// round 14
// speedup vs baseline: 1.8462x; 1.8462x over previous
#include <cuda_runtime.h>
#include <cuda_fp16.h>
#include <cstdint>

#define HIDDEN 128
#define MAX_NODES 100000
#define NBINS_MAX 1600
#define BIN_CAP 1024
#define CNT_STRIDE 64            // 64 ints = 256B: spreads counters across LTS slices
#define NODES_PER_CTA 64
#define PROJ_THREADS 512

// Interleaved per-node projections, fp16, COLUMN-PERMUTED for dense stores:
// row = [src-proj(+b1) perm | dst-proj perm]. Permutation compensated by g_w2p.
__device__ __half g_p[(size_t)MAX_NODES * 256];
__device__ float  g_w2p[128];     // W2 permuted to stored order

// Fixed-capacity bins keyed by src tile (bin = src >> 6). No hist/scan pass.
__device__ int  g_bincnt[NBINS_MAX * CNT_STRIDE];    // 256B-strided counters
__device__ int4 g_esort[(size_t)NBINS_MAX * BIN_CAP]; // {src, dst, edge_id, 0}

__device__ __forceinline__ uint32_t smem_u32(const void* p) {
    uint32_t a;
    asm("{ .reg .u64 t; cvta.to.shared.u64 t, %1; cvt.u32.u64 %0, t; }"
        : "=r"(a) : "l"(p));
    return a;
}

// SMEM layout (dynamic, 98816 B, 1 CTA x 512 thr per SM):
//   [0,512)         b1 (128 f32)
//   [512,16896)     A0: z fp16, 64 rows x 256B, XOR-16B swizzle
//   [16896,33280)   A1: double buffer
//   [33280,98816)   B: W1^T fp16, 256 rows x 256B, XOR-16B swizzle (persistent)
#define SM_B1  0
#define SM_A0  512
#define SM_A1  16896
#define SM_B   33280
#define SMEM_BYTES 98816

// ---------------------------------------------------------------------------
// Phase 1: persistent 512-thread CTA, warp grid 2m x 8n (R11 verbatim, 28.1us).
// ---------------------------------------------------------------------------
__global__ void __launch_bounds__(PROJ_THREADS, 1)
proj_mma_kernel(const float* __restrict__ z,
                const float* __restrict__ W1,
                const float* __restrict__ b1,
                const float* __restrict__ W2,
                int n_nodes, int n_tiles)
{
    extern __shared__ char smem[];
    const uint32_t smem_base = smem_u32(smem);
    const int tid  = threadIdx.x;
    const int lane = tid & 31;
    const int wid  = tid >> 5;
    const int wm = wid >> 3;      // 0..1  (rows 32*wm)
    const int wn = wid & 7;       // 0..7  (cols 32*wn)

    const int zrow = tid >> 3;
    const int zc4  = (tid & 7) * 4;

    float4 zr[4];
    {
        int node0 = blockIdx.x * NODES_PER_CTA;
        int gn = node0 + zrow; if (gn >= n_nodes) gn = n_nodes - 1;
        const float4* zp = (const float4*)(z + (size_t)gn * HIDDEN);
        #pragma unroll
        for (int j = 0; j < 4; j++) zr[j] = zp[zc4 + j];
    }

    if (tid < 128) ((float*)(smem + SM_B1))[tid] = b1[tid];

    // Permuted W2: stored s within 32-col block: s = q*8 + nj*2 + t
    if (blockIdx.x == 0 && tid < 128) {
        int blk = tid >> 5, s = tid & 31;
        int orig = ((s >> 1) & 3) * 8 + (s >> 3) * 2 + (s & 1);
        g_w2p[tid] = W2[blk * 32 + orig];
    }

    // Stage B once: B[n][k] = W1[k][n] (n<128) / W1[128+k][n-128]
    {
        int n = tid >> 1;
        int c = n & 127;
        int rbase = (n < 128) ? 0 : 128;
        int kc0 = (tid & 1) * 16;
        #pragma unroll 4
        for (int kk = 0; kk < 16; kk++) {
            int kc = kc0 + kk;
            float f0 = W1[(size_t)(rbase + kc * 4 + 0) * 128 + c];
            float f1 = W1[(size_t)(rbase + kc * 4 + 1) * 128 + c];
            float f2 = W1[(size_t)(rbase + kc * 4 + 2) * 128 + c];
            float f3 = W1[(size_t)(rbase + kc * 4 + 3) * 128 + c];
            __half2 h01 = __floats2half2_rn(f0, f1);
            __half2 h23 = __floats2half2_rn(f2, f3);
            uint2 v;
            v.x = *(uint32_t*)&h01;
            v.y = *(uint32_t*)&h23;
            uint32_t off = ((uint32_t)(kc * 8)) ^ ((uint32_t)(n & 7) << 4);
            *(uint2*)(smem + SM_B + n * 256 + off) = v;
        }
    }
    __syncthreads();

    float bx[4], by[4];
    #pragma unroll
    for (int nj = 0; nj < 4; nj++) {
        int col = wn * 32 + nj * 8 + ((lane & 3) << 1);
        if (col < 128) {
            float2 bb = *(const float2*)(smem + SM_B1 + col * 4);
            bx[nj] = bb.x; by[nj] = bb.y;
        } else {
            bx[nj] = 0.f; by[nj] = 0.f;
        }
    }

    const uint32_t smB = smem_base + SM_B;
    int buf = 0;

    for (int tile = blockIdx.x; tile < n_tiles; tile += gridDim.x) {
        const int node0 = tile * NODES_PER_CTA;
        const uint32_t smA = smem_base + (buf ? SM_A1 : SM_A0);

        #pragma unroll
        for (int j = 0; j < 4; j++) {
            int c4 = zc4 + j;
            __half2 h01 = __floats2half2_rn(zr[j].x, zr[j].y);
            __half2 h23 = __floats2half2_rn(zr[j].z, zr[j].w);
            uint2 v;
            v.x = *(uint32_t*)&h01;
            v.y = *(uint32_t*)&h23;
            uint32_t off = ((uint32_t)(c4 * 8)) ^ ((uint32_t)(zrow & 7) << 4);
            *(uint2*)(smem + (buf ? SM_A1 : SM_A0) + zrow * 256 + off) = v;
        }
        __syncthreads();

        {
            int nt = tile + gridDim.x;
            if (nt < n_tiles) {
                int gn = nt * NODES_PER_CTA + zrow;
                if (gn >= n_nodes) gn = n_nodes - 1;
                const float4* zp = (const float4*)(z + (size_t)gn * HIDDEN);
                #pragma unroll
                for (int j = 0; j < 4; j++) zr[j] = zp[zc4 + j];
            }
        }

        float acc[2][4][4];
        #pragma unroll
        for (int mi = 0; mi < 2; mi++)
            #pragma unroll
            for (int nj = 0; nj < 4; nj++)
                #pragma unroll
                for (int q = 0; q < 4; q++) acc[mi][nj][q] = 0.0f;

        #pragma unroll
        for (int ks = 0; ks < 8; ks++) {
            uint32_t a[2][4];
            #pragma unroll
            for (int mi = 0; mi < 2; mi++) {
                int r = wm * 32 + mi * 16 + (lane & 15);
                uint32_t kb = (uint32_t)(ks * 32 + ((lane >> 4) << 4));
                uint32_t addr = smA + (uint32_t)(r * 256) + (kb ^ ((uint32_t)(r & 7) << 4));
                asm volatile("ldmatrix.sync.aligned.m8n8.x4.shared.b16 {%0,%1,%2,%3}, [%4];"
                             : "=r"(a[mi][0]), "=r"(a[mi][1]), "=r"(a[mi][2]), "=r"(a[mi][3])
                             : "r"(addr));
            }
            uint32_t b[4][2];
            #pragma unroll
            for (int nj = 0; nj < 4; nj++) {
                int r = wn * 32 + nj * 8 + (lane & 7);
                uint32_t kb = (uint32_t)(ks * 32 + (((lane >> 3) & 1) << 4));
                uint32_t addr = smB + (uint32_t)(r * 256) + (kb ^ ((uint32_t)(r & 7) << 4));
                asm volatile("ldmatrix.sync.aligned.m8n8.x2.shared.b16 {%0,%1}, [%2];"
                             : "=r"(b[nj][0]), "=r"(b[nj][1]) : "r"(addr));
            }
            #pragma unroll
            for (int mi = 0; mi < 2; mi++)
                #pragma unroll
                for (int nj = 0; nj < 4; nj++) {
                    asm volatile(
                        "mma.sync.aligned.m16n8k16.row.col.f32.f16.f16.f32 "
                        "{%0,%1,%2,%3}, {%4,%5,%6,%7}, {%8,%9}, {%0,%1,%2,%3};"
                        : "+f"(acc[mi][nj][0]), "+f"(acc[mi][nj][1]),
                          "+f"(acc[mi][nj][2]), "+f"(acc[mi][nj][3])
                        : "r"(a[mi][0]), "r"(a[mi][1]), "r"(a[mi][2]), "r"(a[mi][3]),
                          "r"(b[nj][0]), "r"(b[nj][1]));
                }
        }

        {
            const int q = lane & 3;
            #pragma unroll
            for (int mi = 0; mi < 2; mi++) {
                int row = wm * 32 + mi * 16 + (lane >> 2);
                int gn0 = node0 + row;
                int gn1 = gn0 + 8;
                uint32_t p0[4], p1[4];
                #pragma unroll
                for (int nj = 0; nj < 4; nj++) {
                    __half2 v0 = __floats2half2_rn(acc[mi][nj][0] + bx[nj],
                                                   acc[mi][nj][1] + by[nj]);
                    __half2 v1 = __floats2half2_rn(acc[mi][nj][2] + bx[nj],
                                                   acc[mi][nj][3] + by[nj]);
                    p0[nj] = *(uint32_t*)&v0;
                    p1[nj] = *(uint32_t*)&v1;
                }
                size_t base0 = (size_t)gn0 * 256 + wn * 32 + q * 8;
                size_t base1 = (size_t)gn1 * 256 + wn * 32 + q * 8;
                if (gn0 < n_nodes) *(uint4*)(g_p + base0) = *(uint4*)p0;
                if (gn1 < n_nodes) *(uint4*)(g_p + base1) = *(uint4*)p1;
            }
        }
        buf ^= 1;
    }
}

// ---------------------------------------------------------------------------
// Binning: clear padded counters, then one scatter pass (no hist/scan).
// ---------------------------------------------------------------------------
__global__ void clear_kernel()
{
    int i = blockIdx.x * blockDim.x + threadIdx.x;
    if (i < NBINS_MAX * CNT_STRIDE) g_bincnt[i] = 0;
}

__global__ void scatter_kernel(const int* __restrict__ ei, int n_edges)
{
    int e = blockIdx.x * blockDim.x + threadIdx.x;
    if (e < n_edges) {
        int s = ei[e];
        int d = ei[n_edges + e];
        int bin = s >> 6;
        int pos = atomicAdd(&g_bincnt[bin * CNT_STRIDE], 1);   // 256B-strided
        if (pos < BIN_CAP)
            g_esort[(size_t)bin * BIN_CAP + pos] = make_int4(s, d, e, 0);
    }
}

// ---------------------------------------------------------------------------
// Phase 2: one CTA per src-tile bin. Src rows (16KB/bin) become L1-resident;
// dst gathers use __ldcg (L2-only) to avoid evicting the hot src tile.
// Per-edge math identical to R8/R11 (bit-identical output, order-independent).
// ---------------------------------------------------------------------------
__global__ void __launch_bounds__(256) edge_kernel(
    const float* __restrict__ b2,
    float* __restrict__ out)
{
    const int bin = blockIdx.x;
    int cnt = g_bincnt[bin * CNT_STRIDE];
    if (cnt <= 0) return;
    if (cnt > BIN_CAP) cnt = BIN_CAP;

    const int4* ebase = g_esort + (size_t)bin * BIN_CAP;
    const int lane = threadIdx.x & 31;
    const int wid  = threadIdx.x >> 5;
    const int half = lane >> 4;
    const int kl   = lane & 15;

    const float4 w0 = *((const float4*)g_w2p + kl * 2);
    const float4 w1 = *((const float4*)g_w2p + kl * 2 + 1);
    const float bb = b2[0];
    const __half2 z2 = __float2half2_rn(0.0f);

    for (int c0 = wid * 8; c0 < cnt; c0 += 64) {   // 8 warps x 8 edges per chunk
        int pe = c0 + half * 4;

        int sv[4], dv[4], ov[4];
        #pragma unroll
        for (int j = 0; j < 4; j++) {
            int idx = pe + j; if (idx >= cnt) idx = cnt - 1;
            int4 en = ebase[idx];
            sv[j] = en.x; dv[j] = en.y; ov[j] = en.z;
        }

        // 8 independent 16B gathers: src (L1-hot tile), dst via L2-only.
        uint4 ra[4], rb[4];
        #pragma unroll
        for (int j = 0; j < 4; j++)
            ra[j] = *(const uint4*)(g_p + (size_t)sv[j] * 256 + kl * 8);
        #pragma unroll
        for (int j = 0; j < 4; j++)
            rb[j] = __ldcg((const uint4*)(g_p + (size_t)dv[j] * 256 + 128 + kl * 8));

        float accv[4];
        #pragma unroll
        for (int j = 0; j < 4; j++) {
            __half2 h0 = __hmax2(__hadd2(*(const __half2*)&ra[j].x, *(const __half2*)&rb[j].x), z2);
            __half2 h1 = __hmax2(__hadd2(*(const __half2*)&ra[j].y, *(const __half2*)&rb[j].y), z2);
            __half2 h2 = __hmax2(__hadd2(*(const __half2*)&ra[j].z, *(const __half2*)&rb[j].z), z2);
            __half2 h3 = __hmax2(__hadd2(*(const __half2*)&ra[j].w, *(const __half2*)&rb[j].w), z2);
            float2 f0 = __half22float2(h0), f1 = __half22float2(h1);
            float2 f2 = __half22float2(h2), f3 = __half22float2(h3);
            float a =       f0.x * w0.x;
            a = fmaf(f0.y, w0.y, a);
            a = fmaf(f1.x, w0.z, a);
            a = fmaf(f1.y, w0.w, a);
            a = fmaf(f2.x, w1.x, a);
            a = fmaf(f2.y, w1.y, a);
            a = fmaf(f3.x, w1.z, a);
            a = fmaf(f3.y, w1.w, a);
            accv[j] = a;
        }

        #pragma unroll
        for (int o = 8; o > 0; o >>= 1) {
            accv[0] += __shfl_xor_sync(0xFFFFFFFFu, accv[0], o);
            accv[1] += __shfl_xor_sync(0xFFFFFFFFu, accv[1], o);
            accv[2] += __shfl_xor_sync(0xFFFFFFFFu, accv[2], o);
            accv[3] += __shfl_xor_sync(0xFFFFFFFFu, accv[3], o);
        }

        if (kl == 0) {
            #pragma unroll
            for (int j = 0; j < 4; j++)
                if (pe + j < cnt) out[ov[j]] = accv[j] + bb;
        }
    }
}

// ---------------------------------------------------------------------------
// Launch
// Inputs: 0 z[f32 N*128], 1 edge_index[i32 2*E], 2 W1[f32 256*128],
//         3 b1[f32 128], 4 W2[f32 128], 5 b2[f32 1]; out f32 [E].
// ---------------------------------------------------------------------------
extern "C" void kernel_launch(void* const* d_in, const int* in_sizes, int n_in,
                              void* d_out, int out_size)
{
    const float* z  = (const float*)d_in[0];
    const int*   ei = (const int*)d_in[1];
    const float* W1 = (const float*)d_in[2];
    const float* b1 = (const float*)d_in[3];
    const float* W2 = (const float*)d_in[4];
    const float* b2 = (const float*)d_in[5];
    float*       out = (float*)d_out;

    int n_nodes = in_sizes[0] / HIDDEN;
    int n_edges = in_sizes[1] / 2;
    int n_tiles = (n_nodes + NODES_PER_CTA - 1) / NODES_PER_CTA;
    int nbins   = (n_nodes + 63) >> 6;

    cudaFuncSetAttribute(proj_mma_kernel,
                         cudaFuncAttributeMaxDynamicSharedMemorySize, SMEM_BYTES);

    // Binning prep (independent of proj output).
    clear_kernel<<<(NBINS_MAX * CNT_STRIDE + 255) / 256, 256>>>();
    int gb = (n_edges + 255) / 256;
    scatter_kernel<<<gb, 256>>>(ei, n_edges);

    int pg = 148;
    if (pg > n_tiles) pg = n_tiles;
    proj_mma_kernel<<<pg, PROJ_THREADS, SMEM_BYTES>>>(z, W1, b1, W2, n_nodes, n_tiles);

    edge_kernel<<<nbins, 256>>>(b2, out);
}

// round 15
// speedup vs baseline: 2.4436x; 1.3236x over previous
#include <cuda_runtime.h>
#include <cuda_fp16.h>
#include <cstdint>

#define HIDDEN 128
#define MAX_NODES 100000
#define NODES_PER_CTA 64
#define PROJ_THREADS 512

// Interleaved per-node projections, fp16, COLUMN-PERMUTED for dense stores:
// row = [src-proj(+b1) perm | dst-proj perm]. Permutation compensated by g_w2p.
__device__ __half g_p[(size_t)MAX_NODES * 256];
__device__ float  g_w2p[128];     // W2 permuted to stored order

__device__ __forceinline__ uint32_t smem_u32(const void* p) {
    uint32_t a;
    asm("{ .reg .u64 t; cvta.to.shared.u64 t, %1; cvt.u32.u64 %0, t; }"
        : "=r"(a) : "l"(p));
    return a;
}

// SMEM layout (dynamic, 98816 B, 1 CTA x 512 thr per SM):
//   [0,512)         b1 (128 f32)
//   [512,16896)     A0: z fp16, 64 rows x 256B, XOR-16B swizzle
//   [16896,33280)   A1: double buffer
//   [33280,98816)   B: W1^T fp16, 256 rows x 256B, XOR-16B swizzle (persistent)
#define SM_B1  0
#define SM_A0  512
#define SM_A1  16896
#define SM_B   33280
#define SMEM_BYTES 98816

// ---------------------------------------------------------------------------
// Phase 1: persistent 512-thread CTA, warp grid 2m x 8n (R11 verbatim, 28.1us).
// ---------------------------------------------------------------------------
__global__ void __launch_bounds__(PROJ_THREADS, 1)
proj_mma_kernel(const float* __restrict__ z,
                const float* __restrict__ W1,
                const float* __restrict__ b1,
                const float* __restrict__ W2,
                int n_nodes, int n_tiles)
{
    extern __shared__ char smem[];
    const uint32_t smem_base = smem_u32(smem);
    const int tid  = threadIdx.x;
    const int lane = tid & 31;
    const int wid  = tid >> 5;
    const int wm = wid >> 3;      // 0..1  (rows 32*wm)
    const int wn = wid & 7;       // 0..7  (cols 32*wn)

    const int zrow = tid >> 3;
    const int zc4  = (tid & 7) * 4;

    float4 zr[4];
    {
        int node0 = blockIdx.x * NODES_PER_CTA;
        int gn = node0 + zrow; if (gn >= n_nodes) gn = n_nodes - 1;
        const float4* zp = (const float4*)(z + (size_t)gn * HIDDEN);
        #pragma unroll
        for (int j = 0; j < 4; j++) zr[j] = zp[zc4 + j];
    }

    if (tid < 128) ((float*)(smem + SM_B1))[tid] = b1[tid];

    // Permuted W2: stored s within 32-col block: s = q*8 + nj*2 + t
    if (blockIdx.x == 0 && tid < 128) {
        int blk = tid >> 5, s = tid & 31;
        int orig = ((s >> 1) & 3) * 8 + (s >> 3) * 2 + (s & 1);
        g_w2p[tid] = W2[blk * 32 + orig];
    }

    // Stage B once: B[n][k] = W1[k][n] (n<128) / W1[128+k][n-128]
    {
        int n = tid >> 1;
        int c = n & 127;
        int rbase = (n < 128) ? 0 : 128;
        int kc0 = (tid & 1) * 16;
        #pragma unroll 4
        for (int kk = 0; kk < 16; kk++) {
            int kc = kc0 + kk;
            float f0 = W1[(size_t)(rbase + kc * 4 + 0) * 128 + c];
            float f1 = W1[(size_t)(rbase + kc * 4 + 1) * 128 + c];
            float f2 = W1[(size_t)(rbase + kc * 4 + 2) * 128 + c];
            float f3 = W1[(size_t)(rbase + kc * 4 + 3) * 128 + c];
            __half2 h01 = __floats2half2_rn(f0, f1);
            __half2 h23 = __floats2half2_rn(f2, f3);
            uint2 v;
            v.x = *(uint32_t*)&h01;
            v.y = *(uint32_t*)&h23;
            uint32_t off = ((uint32_t)(kc * 8)) ^ ((uint32_t)(n & 7) << 4);
            *(uint2*)(smem + SM_B + n * 256 + off) = v;
        }
    }
    __syncthreads();

    float bx[4], by[4];
    #pragma unroll
    for (int nj = 0; nj < 4; nj++) {
        int col = wn * 32 + nj * 8 + ((lane & 3) << 1);
        if (col < 128) {
            float2 bb = *(const float2*)(smem + SM_B1 + col * 4);
            bx[nj] = bb.x; by[nj] = bb.y;
        } else {
            bx[nj] = 0.f; by[nj] = 0.f;
        }
    }

    const uint32_t smB = smem_base + SM_B;
    int buf = 0;

    for (int tile = blockIdx.x; tile < n_tiles; tile += gridDim.x) {
        const int node0 = tile * NODES_PER_CTA;
        const uint32_t smA = smem_base + (buf ? SM_A1 : SM_A0);

        #pragma unroll
        for (int j = 0; j < 4; j++) {
            int c4 = zc4 + j;
            __half2 h01 = __floats2half2_rn(zr[j].x, zr[j].y);
            __half2 h23 = __floats2half2_rn(zr[j].z, zr[j].w);
            uint2 v;
            v.x = *(uint32_t*)&h01;
            v.y = *(uint32_t*)&h23;
            uint32_t off = ((uint32_t)(c4 * 8)) ^ ((uint32_t)(zrow & 7) << 4);
            *(uint2*)(smem + (buf ? SM_A1 : SM_A0) + zrow * 256 + off) = v;
        }
        __syncthreads();

        {
            int nt = tile + gridDim.x;
            if (nt < n_tiles) {
                int gn = nt * NODES_PER_CTA + zrow;
                if (gn >= n_nodes) gn = n_nodes - 1;
                const float4* zp = (const float4*)(z + (size_t)gn * HIDDEN);
                #pragma unroll
                for (int j = 0; j < 4; j++) zr[j] = zp[zc4 + j];
            }
        }

        float acc[2][4][4];
        #pragma unroll
        for (int mi = 0; mi < 2; mi++)
            #pragma unroll
            for (int nj = 0; nj < 4; nj++)
                #pragma unroll
                for (int q = 0; q < 4; q++) acc[mi][nj][q] = 0.0f;

        #pragma unroll
        for (int ks = 0; ks < 8; ks++) {
            uint32_t a[2][4];
            #pragma unroll
            for (int mi = 0; mi < 2; mi++) {
                int r = wm * 32 + mi * 16 + (lane & 15);
                uint32_t kb = (uint32_t)(ks * 32 + ((lane >> 4) << 4));
                uint32_t addr = smA + (uint32_t)(r * 256) + (kb ^ ((uint32_t)(r & 7) << 4));
                asm volatile("ldmatrix.sync.aligned.m8n8.x4.shared.b16 {%0,%1,%2,%3}, [%4];"
                             : "=r"(a[mi][0]), "=r"(a[mi][1]), "=r"(a[mi][2]), "=r"(a[mi][3])
                             : "r"(addr));
            }
            uint32_t b[4][2];
            #pragma unroll
            for (int nj = 0; nj < 4; nj++) {
                int r = wn * 32 + nj * 8 + (lane & 7);
                uint32_t kb = (uint32_t)(ks * 32 + (((lane >> 3) & 1) << 4));
                uint32_t addr = smB + (uint32_t)(r * 256) + (kb ^ ((uint32_t)(r & 7) << 4));
                asm volatile("ldmatrix.sync.aligned.m8n8.x2.shared.b16 {%0,%1}, [%2];"
                             : "=r"(b[nj][0]), "=r"(b[nj][1]) : "r"(addr));
            }
            #pragma unroll
            for (int mi = 0; mi < 2; mi++)
                #pragma unroll
                for (int nj = 0; nj < 4; nj++) {
                    asm volatile(
                        "mma.sync.aligned.m16n8k16.row.col.f32.f16.f16.f32 "
                        "{%0,%1,%2,%3}, {%4,%5,%6,%7}, {%8,%9}, {%0,%1,%2,%3};"
                        : "+f"(acc[mi][nj][0]), "+f"(acc[mi][nj][1]),
                          "+f"(acc[mi][nj][2]), "+f"(acc[mi][nj][3])
                        : "r"(a[mi][0]), "r"(a[mi][1]), "r"(a[mi][2]), "r"(a[mi][3]),
                          "r"(b[nj][0]), "r"(b[nj][1]));
                }
        }

        {
            const int q = lane & 3;
            #pragma unroll
            for (int mi = 0; mi < 2; mi++) {
                int row = wm * 32 + mi * 16 + (lane >> 2);
                int gn0 = node0 + row;
                int gn1 = gn0 + 8;
                uint32_t p0[4], p1[4];
                #pragma unroll
                for (int nj = 0; nj < 4; nj++) {
                    __half2 v0 = __floats2half2_rn(acc[mi][nj][0] + bx[nj],
                                                   acc[mi][nj][1] + by[nj]);
                    __half2 v1 = __floats2half2_rn(acc[mi][nj][2] + bx[nj],
                                                   acc[mi][nj][3] + by[nj]);
                    p0[nj] = *(uint32_t*)&v0;
                    p1[nj] = *(uint32_t*)&v1;
                }
                size_t base0 = (size_t)gn0 * 256 + wn * 32 + q * 8;
                size_t base1 = (size_t)gn1 * 256 + wn * 32 + q * 8;
                if (gn0 < n_nodes) *(uint4*)(g_p + base0) = *(uint4*)p0;
                if (gn1 < n_nodes) *(uint4*)(g_p + base1) = *(uint4*)p1;
            }
        }
        buf ^= 1;
    }
}

// ---------------------------------------------------------------------------
// Phase 2: EIGHT edges per warp; each half-warp owns 4 edges (R8 math,
// bit-identical). Block size 128 (not 256): at 38 regs the RF quantizes to
// ~13 blocks/SM = 52 warps (~81% occ) vs 42 warps at 256-thr blocks.
// ---------------------------------------------------------------------------
__global__ void __launch_bounds__(128) edge_kernel(
    const int* __restrict__ ei,
    const float* __restrict__ b2,
    float* __restrict__ out,
    int n_edges)
{
    int warp = (int)((blockIdx.x * (unsigned)blockDim.x + threadIdx.x) >> 5);
    int lane = threadIdx.x & 31;
    int ebase = warp * 8;
    if (ebase >= n_edges) return;

    int half = lane >> 4;         // 0/1
    int kl   = lane & 15;
    int e0 = ebase + half * 4;    // this half-warp's first edge

    int sv[4], dv[4];
    bool fast = (ebase + 8 <= n_edges) && ((n_edges & 3) == 0);
    if (fast) {
        int4 s4 = *(const int4*)(ei + e0);
        int4 d4 = *(const int4*)(ei + n_edges + e0);
        sv[0] = s4.x; sv[1] = s4.y; sv[2] = s4.z; sv[3] = s4.w;
        dv[0] = d4.x; dv[1] = d4.y; dv[2] = d4.z; dv[3] = d4.w;
    } else {
        #pragma unroll
        for (int j = 0; j < 4; j++) {
            int c = e0 + j; if (c >= n_edges) c = n_edges - 1;
            sv[j] = ei[c]; dv[j] = ei[n_edges + c];
        }
    }

    // 8 independent 16B gathers.
    uint4 ra[4], rb[4];
    #pragma unroll
    for (int j = 0; j < 4; j++)
        ra[j] = *(const uint4*)(g_p + (size_t)sv[j] * 256 + kl * 8);
    #pragma unroll
    for (int j = 0; j < 4; j++)
        rb[j] = *(const uint4*)(g_p + (size_t)dv[j] * 256 + 128 + kl * 8);

    const float4 w0 = *((const float4*)g_w2p + kl * 2);
    const float4 w1 = *((const float4*)g_w2p + kl * 2 + 1);
    const __half2 z2 = __float2half2_rn(0.0f);

    float accv[4];
    #pragma unroll
    for (int j = 0; j < 4; j++) {
        __half2 h0 = __hmax2(__hadd2(*(const __half2*)&ra[j].x, *(const __half2*)&rb[j].x), z2);
        __half2 h1 = __hmax2(__hadd2(*(const __half2*)&ra[j].y, *(const __half2*)&rb[j].y), z2);
        __half2 h2 = __hmax2(__hadd2(*(const __half2*)&ra[j].z, *(const __half2*)&rb[j].z), z2);
        __half2 h3 = __hmax2(__hadd2(*(const __half2*)&ra[j].w, *(const __half2*)&rb[j].w), z2);
        float2 f0 = __half22float2(h0), f1 = __half22float2(h1);
        float2 f2 = __half22float2(h2), f3 = __half22float2(h3);
        float a =       f0.x * w0.x;
        a = fmaf(f0.y, w0.y, a);
        a = fmaf(f1.x, w0.z, a);
        a = fmaf(f1.y, w0.w, a);
        a = fmaf(f2.x, w1.x, a);
        a = fmaf(f2.y, w1.y, a);
        a = fmaf(f3.x, w1.z, a);
        a = fmaf(f3.y, w1.w, a);
        accv[j] = a;
    }

    #pragma unroll
    for (int o = 8; o > 0; o >>= 1) {
        accv[0] += __shfl_xor_sync(0xFFFFFFFFu, accv[0], o);
        accv[1] += __shfl_xor_sync(0xFFFFFFFFu, accv[1], o);
        accv[2] += __shfl_xor_sync(0xFFFFFFFFu, accv[2], o);
        accv[3] += __shfl_xor_sync(0xFFFFFFFFu, accv[3], o);
    }

    if (kl == 0) {
        float bb = b2[0];
        if (e0 + 4 <= n_edges) {
            float4 o4 = make_float4(accv[0] + bb, accv[1] + bb,
                                    accv[2] + bb, accv[3] + bb);
            *(float4*)(out + e0) = o4;
        } else {
            #pragma unroll
            for (int j = 0; j < 4; j++)
                if (e0 + j < n_edges) out[e0 + j] = accv[j] + bb;
        }
    }
}

// ---------------------------------------------------------------------------
// Launch
// Inputs: 0 z[f32 N*128], 1 edge_index[i32 2*E], 2 W1[f32 256*128],
//         3 b1[f32 128], 4 W2[f32 128], 5 b2[f32 1]; out f32 [E].
// ---------------------------------------------------------------------------
extern "C" void kernel_launch(void* const* d_in, const int* in_sizes, int n_in,
                              void* d_out, int out_size)
{
    const float* z  = (const float*)d_in[0];
    const int*   ei = (const int*)d_in[1];
    const float* W1 = (const float*)d_in[2];
    const float* b1 = (const float*)d_in[3];
    const float* W2 = (const float*)d_in[4];
    const float* b2 = (const float*)d_in[5];
    float*       out = (float*)d_out;

    int n_nodes = in_sizes[0] / HIDDEN;
    int n_edges = in_sizes[1] / 2;
    int n_tiles = (n_nodes + NODES_PER_CTA - 1) / NODES_PER_CTA;

    cudaFuncSetAttribute(proj_mma_kernel,
                         cudaFuncAttributeMaxDynamicSharedMemorySize, SMEM_BYTES);

    int pg = 148;                 // persistent: 1 x 512-thread CTA per SM
    if (pg > n_tiles) pg = n_tiles;
    proj_mma_kernel<<<pg, PROJ_THREADS, SMEM_BYTES>>>(z, W1, b1, W2, n_nodes, n_tiles);

    int eb = (n_edges + 31) / 32;     // 32 edges per 128-thread block
    edge_kernel<<<eb, 128>>>(ei, b2, out, n_edges);
}